// round 16
// baseline (speedup 1.0000x reference)
#include <cuda_runtime.h>
#include <cuda_fp16.h>
#include <cstdint>
#include <cstddef>

// ============================ problem constants ============================
static constexpr int K_FEAT = 4096;   // in_features (K)
static constexpr int N_FEAT = 4096;   // out_features (N)
static constexpr int M_ROWS = 8192;   // 4 * 2048 (M)

static constexpr int TILE_M = 128;
static constexpr int TILE_N = 256;
static constexpr int TILE_K = 32;                  // halves per stage row
static constexpr int STAGES = 6;                   // 6 k-tile buffers
static constexpr int KT     = K_FEAT / TILE_K;     // 128 k-iterations

// SMEM stage layout: padded rows of 32 halves -> 80 bytes (64 data + 16 pad)
static constexpr int ROW_BYTES = 80;
static constexpr int A_STAGE   = TILE_M * ROW_BYTES;            // 10240
static constexpr int B_STAGE   = TILE_N * ROW_BYTES;            // 20480
static constexpr int STAGE_BYTES = A_STAGE + B_STAGE;           // 30720
static constexpr int SMEM_BYTES  = STAGES * STAGE_BYTES;        // 184320

// ============================ scratch (no cudaMalloc allowed) ==============
__device__ __align__(16) __half g_x_f16[(size_t)M_ROWS * K_FEAT];  // 64 MB
__device__ __align__(16) __half g_w_f16[(size_t)N_FEAT * K_FEAT];  // 32 MB

// ============================ PTX helpers ==================================
__device__ __forceinline__ unsigned smem_u32(const void* p) {
    unsigned a;
    asm("{ .reg .u64 t; cvta.to.shared.u64 t, %1; cvt.u32.u64 %0, t; }" : "=r"(a) : "l"(p));
    return a;
}
__device__ __forceinline__ void cp_async16(unsigned dst, const void* src) {
    asm volatile("cp.async.cg.shared.global [%0], [%1], 16;"
                 :: "r"(dst), "l"(__cvta_generic_to_global(src)));
}
#define CP_COMMIT() asm volatile("cp.async.commit_group;" ::: "memory")
#define CP_WAIT2()  asm volatile("cp.async.wait_group 2;" ::: "memory")
#define CP_WAIT0()  asm volatile("cp.async.wait_group 0;" ::: "memory")

__device__ __forceinline__ void ldsm_x4(unsigned& r0, unsigned& r1, unsigned& r2, unsigned& r3,
                                        unsigned addr) {
    asm volatile("ldmatrix.sync.aligned.m8n8.x4.shared.b16 {%0,%1,%2,%3}, [%4];"
                 : "=r"(r0), "=r"(r1), "=r"(r2), "=r"(r3) : "r"(addr));
}
__device__ __forceinline__ void mma_16816(float* c, unsigned a0, unsigned a1, unsigned a2,
                                          unsigned a3, unsigned b0, unsigned b1) {
    asm volatile(
        "mma.sync.aligned.m16n8k16.row.col.f32.f16.f16.f32 "
        "{%0,%1,%2,%3}, {%4,%5,%6,%7}, {%8,%9}, {%0,%1,%2,%3};"
        : "+f"(c[0]), "+f"(c[1]), "+f"(c[2]), "+f"(c[3])
        : "r"(a0), "r"(a1), "r"(a2), "r"(a3), "r"(b0), "r"(b1));
}

// ============================ fused prologue ===============================
__global__ void prologue_kernel(const float4* __restrict__ x, int n4,
                                const int* __restrict__ wp,
                                const float* __restrict__ params, int npk) {
    const int stride = gridDim.x * blockDim.x;
    const int t0 = blockIdx.x * blockDim.x + threadIdx.x;
    uint2* __restrict__ xo = reinterpret_cast<uint2*>(g_x_f16);
    for (int i = t0; i < n4; i += stride) {
        float4 v = x[i];
        __half2 a = __floats2half2_rn(v.x, v.y);
        __half2 b = __floats2half2_rn(v.z, v.w);
        uint2 u;
        u.x = *reinterpret_cast<const unsigned*>(&a);
        u.y = *reinterpret_cast<const unsigned*>(&b);
        xo[i] = u;
    }
    __half2* __restrict__ wo = reinterpret_cast<__half2*>(g_w_f16);
    for (int i = t0; i < npk; i += stride) {
        int g = i >> 7;                     // 128 packed int32 per group of 256 values
        float s = params[2 * g];
        float z = params[2 * g + 1];
        int p = wp[i];
        float lo = (float)(p & 15);
        float hi = (float)((p >> 4) & 15);
        wo[i] = __floats2half2_rn(fmaf(lo, s, z), fmaf(hi, s, z));
    }
}

// ============================ GEMM kernel ==================================
// CTA: 128x256, 512 threads = 16 warps, warp grid 2(M) x 8(N), warp tile
// 64x32. mma.sync.m16n8k16 fp16->fp32. R14 base (703.6us: stagger + single
// barrier) with TWO k-tiles per barrier: 6 stage buffers, loop kt += 2, one
// CP_WAIT + one __syncthreads per pair -> 64 barrier rounds instead of 128.
// Loads for k-tiles kt+4, kt+5 target buffers consumed in the PREVIOUS pair,
// ordered by this pair's barrier (same proof as the R13 single-barrier).
__global__ void __launch_bounds__(512, 1) gemm_f16_kernel(float* __restrict__ out) {
    extern __shared__ __align__(128) char smem[];
    const unsigned sb = smem_u32(smem);
    const int tid  = threadIdx.x;
    const int wid  = tid >> 5;
    const int lane = tid & 31;
    const int warp_m = wid & 1;      // 0..1
    const int warp_n = wid >> 1;     // 0..7
    const unsigned sflip = (unsigned)(wid & 1);   // k16-step stagger
    const int ntile = blockIdx.x;    // 16 tiles of 256
    const int mtile = blockIdx.y;    // 64 tiles of 128

    const char* aG = reinterpret_cast<const char*>(g_x_f16)
                   + (size_t)(mtile * TILE_M) * (K_FEAT * 2);
    const char* bG = reinterpret_cast<const char*>(g_w_f16)
                   + (size_t)(ntile * TILE_N) * (K_FEAT * 2);

    // ---- per-thread cp.async assignments (3 x 16B chunks per thread) ----
    auto load_stage = [&](int kt, int buf) {
        const unsigned stage = sb + buf * STAGE_BYTES;
        {   // A chunk
            int idx = tid;                    // 0..511
            int r = idx >> 2, c = idx & 3;
            cp_async16(stage + r * ROW_BYTES + c * 16,
                       aG + (size_t)r * (K_FEAT * 2) + (size_t)kt * (TILE_K * 2) + c * 16);
        }
        #pragma unroll
        for (int i = 0; i < 2; ++i) {         // B chunks
            int idx = tid + i * 512;          // 0..1023
            int r = idx >> 2, c = idx & 3;
            cp_async16(stage + A_STAGE + r * ROW_BYTES + c * 16,
                       bG + (size_t)r * (K_FEAT * 2) + (size_t)kt * (TILE_K * 2) + c * 16);
        }
    };

    // ---- ldmatrix per-thread base offsets ----
    unsigned aOff[4];
    #pragma unroll
    for (int mt = 0; mt < 4; ++mt)
        aOff[mt] = (unsigned)((warp_m * 64 + mt * 16 + (lane & 15)) * ROW_BYTES
                              + (lane >> 4) * 16);
    unsigned bOff[2];
    #pragma unroll
    for (int nt2 = 0; nt2 < 2; ++nt2)
        bOff[nt2] = (unsigned)((warp_n * 32 + nt2 * 16 + ((lane >> 1) & 8) + (lane & 7)) * ROW_BYTES
                               + ((lane >> 3) & 1) * 16);

    float c[4][4][4];
    #pragma unroll
    for (int i = 0; i < 4; ++i)
        #pragma unroll
        for (int j = 0; j < 4; ++j)
            #pragma unroll
            for (int v = 0; v < 4; ++v) c[i][j][v] = 0.0f;

    // ---- compute one k-tile (two staggered k16 steps) from buffer buf ----
    auto compute_tile = [&](int buf) {
        const unsigned aBase = sb + buf * STAGE_BYTES;
        const unsigned bBase = aBase + A_STAGE;
        #pragma unroll
        for (int s = 0; s < 2; ++s) {
            const unsigned ks = ((unsigned)s ^ sflip) * 32;   // 16 halves = 32 B
            unsigned a[4][4];
            #pragma unroll
            for (int mt = 0; mt < 4; ++mt)
                ldsm_x4(a[mt][0], a[mt][1], a[mt][2], a[mt][3], aBase + aOff[mt] + ks);
            unsigned b[4][2];
            #pragma unroll
            for (int nt2 = 0; nt2 < 2; ++nt2) {
                unsigned r0, r1, r2, r3;
                ldsm_x4(r0, r1, r2, r3, bBase + bOff[nt2] + ks);
                b[2 * nt2][0] = r0; b[2 * nt2][1] = r1;
                b[2 * nt2 + 1][0] = r2; b[2 * nt2 + 1][1] = r3;
            }
            #pragma unroll
            for (int mt = 0; mt < 4; ++mt)
                #pragma unroll
                for (int nt = 0; nt < 4; ++nt)
                    mma_16816(c[mt][nt], a[mt][0], a[mt][1], a[mt][2], a[mt][3],
                              b[nt][0], b[nt][1]);
        }
    };

    // ---- pipeline prologue: k-tiles 0..3 into buffers 0..3 ----
    #pragma unroll
    for (int s = 0; s < 4; ++s) { load_stage(s, s); CP_COMMIT(); }

    // ---- mainloop: one barrier per TWO k-tiles ----
    #pragma unroll 1
    for (int kt = 0; kt < KT; kt += 2) {
        CP_WAIT2();                      // k-tiles kt and kt+1 have landed
        __syncthreads();

        compute_tile(kt % STAGES);
        compute_tile((kt + 1) % STAGES);

        // loads in the shadow of compute; targets were consumed last pair.
        if (kt + 4 < KT) load_stage(kt + 4, (kt + 4) % STAGES);
        CP_COMMIT();
        if (kt + 5 < KT) load_stage(kt + 5, (kt + 5) % STAGES);
        CP_COMMIT();
    }
    CP_WAIT0();

    // ---- epilogue: direct fp32 stores ----
    const int mwbase = mtile * TILE_M + warp_m * 64;
    const int nwbase = ntile * TILE_N + warp_n * 32;
    const int qrow = lane >> 2;          // 0..7
    const int qcol = (lane & 3) * 2;     // 0,2,4,6
    #pragma unroll
    for (int mt = 0; mt < 4; ++mt) {
        #pragma unroll
        for (int nt = 0; nt < 4; ++nt) {
            const int m0 = mwbase + mt * 16 + qrow;
            const int n0 = nwbase + nt * 8 + qcol;
            float2 v0 = make_float2(c[mt][nt][0], c[mt][nt][1]);
            float2 v1 = make_float2(c[mt][nt][2], c[mt][nt][3]);
            *reinterpret_cast<float2*>(out + (size_t)m0 * N_FEAT + n0) = v0;
            *reinterpret_cast<float2*>(out + (size_t)(m0 + 8) * N_FEAT + n0) = v1;
        }
    }
}

// ============================ launch =======================================
extern "C" void kernel_launch(void* const* d_in, const int* in_sizes, int n_in,
                              void* d_out, int out_size) {
    const float* x       = (const float*)d_in[0];
    const int*   wpacked = (const int*)d_in[1];
    const float* wparams = (const float*)d_in[2];
    float* out = (float*)d_out;

    cudaFuncSetAttribute(gemm_f16_kernel, cudaFuncAttributeMaxDynamicSharedMemorySize,
                         SMEM_BYTES);

    const int n4  = (M_ROWS * K_FEAT) / 4;         // 8,388,608 float4s
    const int npk = (N_FEAT * K_FEAT) / 2;         // 8,388,608 packed int32s
    prologue_kernel<<<4096, 256>>>(reinterpret_cast<const float4*>(x), n4,
                                   wpacked, wparams, npk);

    dim3 grid(N_FEAT / TILE_N, M_ROWS / TILE_M);   // (16, 64)
    gemm_f16_kernel<<<grid, 512, SMEM_BYTES>>>(out);
}

// round 17
// speedup vs baseline: 1.2355x; 1.2355x over previous
#include <cuda_runtime.h>
#include <cuda_fp16.h>
#include <cstdint>
#include <cstddef>

// ============================ problem constants ============================
static constexpr int K_FEAT = 4096;   // in_features (K)
static constexpr int N_FEAT = 4096;   // out_features (N)
static constexpr int M_ROWS = 8192;   // 4 * 2048 (M)

static constexpr int TILE_M = 128;
static constexpr int TILE_N = 256;
static constexpr int TILE_K = 32;                  // halves per stage row
static constexpr int STAGES = 4;
static constexpr int KT     = K_FEAT / TILE_K;     // 128 k-iterations

// SMEM stage layout: padded rows of 32 halves -> 80 bytes (64 data + 16 pad)
static constexpr int ROW_BYTES = 80;
static constexpr int A_STAGE   = TILE_M * ROW_BYTES;            // 10240
static constexpr int B_STAGE   = TILE_N * ROW_BYTES;            // 20480
static constexpr int STAGE_BYTES = A_STAGE + B_STAGE;           // 30720
static constexpr int MBAR_BYTES  = 128;            // full[4] + empty[4] + pad
static constexpr int SMEM_BYTES  = MBAR_BYTES + STAGES * STAGE_BYTES; // 123008

// ============================ scratch (no cudaMalloc allowed) ==============
__device__ __align__(16) __half g_x_f16[(size_t)M_ROWS * K_FEAT];  // 64 MB
__device__ __align__(16) __half g_w_f16[(size_t)N_FEAT * K_FEAT];  // 32 MB

// ============================ PTX helpers ==================================
__device__ __forceinline__ unsigned smem_u32(const void* p) {
    unsigned a;
    asm("{ .reg .u64 t; cvta.to.shared.u64 t, %1; cvt.u32.u64 %0, t; }" : "=r"(a) : "l"(p));
    return a;
}
__device__ __forceinline__ void cp_async16(unsigned dst, const void* src) {
    asm volatile("cp.async.cg.shared.global [%0], [%1], 16;"
                 :: "r"(dst), "l"(__cvta_generic_to_global(src)));
}
// All prior cp.asyncs of this thread arrive (one count) on mbar when complete.
__device__ __forceinline__ void cp_async_mbar_arrive(unsigned mbar) {
    asm volatile("cp.async.mbarrier.arrive.noinc.shared::cta.b64 [%0];"
                 :: "r"(mbar) : "memory");
}
__device__ __forceinline__ void mbar_init(unsigned mbar, unsigned cnt) {
    asm volatile("mbarrier.init.shared.b64 [%0], %1;" :: "r"(mbar), "r"(cnt) : "memory");
}
__device__ __forceinline__ void mbar_arrive(unsigned mbar) {
    asm volatile("mbarrier.arrive.shared.b64 _, [%0];" :: "r"(mbar) : "memory");
}
// acquire wait (consumer: generic LDSM reads follow)
__device__ __forceinline__ void mbar_wait_acq(unsigned mbar, unsigned parity) {
    unsigned done;
    asm volatile(
        "{\n\t.reg .pred p;\n\t"
        "mbarrier.try_wait.parity.acquire.cta.shared::cta.b64 p, [%1], %2;\n\t"
        "selp.b32 %0, 1, 0, p;\n\t}"
        : "=r"(done) : "r"(mbar), "r"(parity) : "memory");
    if (!done) {
        asm volatile(
            "{\n\t.reg .pred P1;\n\t"
            "WLA_%=:\n\t"
            "mbarrier.try_wait.parity.acquire.cta.shared::cta.b64 P1, [%0], %1, 0x989680;\n\t"
            "@P1 bra.uni WDA_%=;\n\t"
            "bra.uni WLA_%=;\n\t"
            "WDA_%=:\n\t}"
            :: "r"(mbar), "r"(parity) : "memory");
    }
}
// relaxed wait (producer: post-wait accesses are async-proxy cp.async only)
__device__ __forceinline__ void mbar_wait_rlx(unsigned mbar, unsigned parity) {
    unsigned done;
    asm volatile(
        "{\n\t.reg .pred p;\n\t"
        "mbarrier.try_wait.parity.relaxed.cta.shared::cta.b64 p, [%1], %2, 0x989680;\n\t"
        "selp.b32 %0, 1, 0, p;\n\t}"
        : "=r"(done) : "r"(mbar), "r"(parity) : "memory");
    if (!done) {
        asm volatile(
            "{\n\t.reg .pred P1;\n\t"
            "WLR_%=:\n\t"
            "mbarrier.try_wait.parity.relaxed.cta.shared::cta.b64 P1, [%0], %1, 0x989680;\n\t"
            "@P1 bra.uni WDR_%=;\n\t"
            "bra.uni WLR_%=;\n\t"
            "WDR_%=:\n\t}"
            :: "r"(mbar), "r"(parity) : "memory");
    }
}

__device__ __forceinline__ void ldsm_x4(unsigned& r0, unsigned& r1, unsigned& r2, unsigned& r3,
                                        unsigned addr) {
    asm volatile("ldmatrix.sync.aligned.m8n8.x4.shared.b16 {%0,%1,%2,%3}, [%4];"
                 : "=r"(r0), "=r"(r1), "=r"(r2), "=r"(r3) : "r"(addr));
}
__device__ __forceinline__ void mma_16816(float* c, unsigned a0, unsigned a1, unsigned a2,
                                          unsigned a3, unsigned b0, unsigned b1) {
    asm volatile(
        "mma.sync.aligned.m16n8k16.row.col.f32.f16.f16.f32 "
        "{%0,%1,%2,%3}, {%4,%5,%6,%7}, {%8,%9}, {%0,%1,%2,%3};"
        : "+f"(c[0]), "+f"(c[1]), "+f"(c[2]), "+f"(c[3])
        : "r"(a0), "r"(a1), "r"(a2), "r"(a3), "r"(b0), "r"(b1));
}

// ============================ fused prologue ===============================
__global__ void prologue_kernel(const float4* __restrict__ x, int n4,
                                const int* __restrict__ wp,
                                const float* __restrict__ params, int npk) {
    const int stride = gridDim.x * blockDim.x;
    const int t0 = blockIdx.x * blockDim.x + threadIdx.x;
    uint2* __restrict__ xo = reinterpret_cast<uint2*>(g_x_f16);
    for (int i = t0; i < n4; i += stride) {
        float4 v = x[i];
        __half2 a = __floats2half2_rn(v.x, v.y);
        __half2 b = __floats2half2_rn(v.z, v.w);
        uint2 u;
        u.x = *reinterpret_cast<const unsigned*>(&a);
        u.y = *reinterpret_cast<const unsigned*>(&b);
        xo[i] = u;
    }
    __half2* __restrict__ wo = reinterpret_cast<__half2*>(g_w_f16);
    for (int i = t0; i < npk; i += stride) {
        int g = i >> 7;                     // 128 packed int32 per group of 256 values
        float s = params[2 * g];
        float z = params[2 * g + 1];
        int p = wp[i];
        float lo = (float)(p & 15);
        float hi = (float)((p >> 4) & 15);
        wo[i] = __floats2half2_rn(fmaf(lo, s, z), fmaf(hi, s, z));
    }
}

// ============================ GEMM kernel ==================================
// R14 compute body (stagger, 64x32 warp tiles, 4 stages, loads after compute)
// with the per-iteration __syncthreads replaced by an mbarrier pipeline:
//   full[s]:  512 expected arrivals (cp.async.mbarrier.arrive.noinc per thread)
//   empty[s]: 16 expected arrivals (one per warp after it finishes reading s)
// Consumers try_wait on full -> NO thread convergence: warps keep their skew
// and cover each other's LDSM/MMA phases. Producers wait empty with ~2 iters
// of slack before overwriting a buffer.
__global__ void __launch_bounds__(512, 1) gemm_f16_kernel(float* __restrict__ out) {
    extern __shared__ __align__(128) char smem[];
    const unsigned sb = smem_u32(smem);
    const unsigned stage0 = sb + MBAR_BYTES;
    const int tid  = threadIdx.x;
    const int wid  = tid >> 5;
    const int lane = tid & 31;
    const int warp_m = wid & 1;      // 0..1
    const int warp_n = wid >> 1;     // 0..7
    const unsigned sflip = (unsigned)(wid & 1);   // k16-step stagger
    const int ntile = blockIdx.x;    // 16 tiles of 256
    const int mtile = blockIdx.y;    // 64 tiles of 128

    auto full_mb  = [&](int s) { return sb + (unsigned)(s * 8); };
    auto empty_mb = [&](int s) { return sb + 32u + (unsigned)(s * 8); };

    if (tid == 0) {
        #pragma unroll
        for (int s = 0; s < STAGES; ++s) {
            mbar_init(full_mb(s), 512);   // one arrival per thread (cp.async-gated)
            mbar_init(empty_mb(s), 16);   // one arrival per warp
        }
    }
    __syncthreads();                      // only CTA-wide barrier in the kernel

    const char* aG = reinterpret_cast<const char*>(g_x_f16)
                   + (size_t)(mtile * TILE_M) * (K_FEAT * 2);
    const char* bG = reinterpret_cast<const char*>(g_w_f16)
                   + (size_t)(ntile * TILE_N) * (K_FEAT * 2);

    // ---- per-thread cp.async assignments (3 x 16B chunks per thread) ----
    auto load_stage = [&](int kt, int buf) {
        const unsigned stage = stage0 + buf * STAGE_BYTES;
        {   // A chunk
            int idx = tid;                    // 0..511
            int r = idx >> 2, c = idx & 3;
            cp_async16(stage + r * ROW_BYTES + c * 16,
                       aG + (size_t)r * (K_FEAT * 2) + (size_t)kt * (TILE_K * 2) + c * 16);
        }
        #pragma unroll
        for (int i = 0; i < 2; ++i) {         // B chunks
            int idx = tid + i * 512;          // 0..1023
            int r = idx >> 2, c = idx & 3;
            cp_async16(stage + A_STAGE + r * ROW_BYTES + c * 16,
                       bG + (size_t)r * (K_FEAT * 2) + (size_t)kt * (TILE_K * 2) + c * 16);
        }
    };

    // ---- ldmatrix per-thread base offsets ----
    unsigned aOff[4];
    #pragma unroll
    for (int mt = 0; mt < 4; ++mt)
        aOff[mt] = (unsigned)((warp_m * 64 + mt * 16 + (lane & 15)) * ROW_BYTES
                              + (lane >> 4) * 16);
    unsigned bOff[2];
    #pragma unroll
    for (int nt2 = 0; nt2 < 2; ++nt2)
        bOff[nt2] = (unsigned)((warp_n * 32 + nt2 * 16 + ((lane >> 1) & 8) + (lane & 7)) * ROW_BYTES
                               + ((lane >> 3) & 1) * 16);

    float c[4][4][4];
    #pragma unroll
    for (int i = 0; i < 4; ++i)
        #pragma unroll
        for (int j = 0; j < 4; ++j)
            #pragma unroll
            for (int v = 0; v < 4; ++v) c[i][j][v] = 0.0f;

    // ---- pipeline prologue: fill buffers 0..2 ----
    #pragma unroll
    for (int s = 0; s < STAGES - 1; ++s) {
        load_stage(s, s);
        cp_async_mbar_arrive(full_mb(s));   // arrival fires when this thread's loads land
    }

    // ---- mainloop: full-wait, compute, empty-arrive, empty-wait, load ----
    #pragma unroll 1
    for (int kt = 0; kt < KT; ++kt) {
        const int buf = kt & (STAGES - 1);
        const unsigned cons_par = ((unsigned)kt >> 2) & 1u;
        mbar_wait_acq(full_mb(buf), cons_par);

        const unsigned aBase = stage0 + buf * STAGE_BYTES;
        const unsigned bBase = aBase + A_STAGE;

        #pragma unroll
        for (int s = 0; s < 2; ++s) {                 // two k16 steps, staggered
            const unsigned ks = ((unsigned)s ^ sflip) * 32;
            unsigned a[4][4];
            #pragma unroll
            for (int mt = 0; mt < 4; ++mt)
                ldsm_x4(a[mt][0], a[mt][1], a[mt][2], a[mt][3], aBase + aOff[mt] + ks);
            unsigned b[4][2];
            #pragma unroll
            for (int nt2 = 0; nt2 < 2; ++nt2) {
                unsigned r0, r1, r2, r3;
                ldsm_x4(r0, r1, r2, r3, bBase + bOff[nt2] + ks);
                b[2 * nt2][0] = r0; b[2 * nt2][1] = r1;
                b[2 * nt2 + 1][0] = r2; b[2 * nt2 + 1][1] = r3;
            }
            #pragma unroll
            for (int mt = 0; mt < 4; ++mt)
                #pragma unroll
                for (int nt = 0; nt < 4; ++nt)
                    mma_16816(c[mt][nt], a[mt][0], a[mt][1], a[mt][2], a[mt][3],
                              b[nt][0], b[nt][1]);
        }

        // this warp is done reading buf (LDSMs retired before this point)
        __syncwarp();
        if (lane == 0) mbar_arrive(empty_mb(buf));

        // producer: refill buffer (kt+3)&3 == (kt-1)&3 once all 16 warps have
        // consumed its previous fill (~2 iterations of slack).
        const int pf = kt + STAGES - 1;
        if (pf < KT) {
            const int pbuf = pf & (STAGES - 1);
            const unsigned prod_par = ((((unsigned)pf >> 2) & 1u) ^ 1u);
            mbar_wait_rlx(empty_mb(pbuf), prod_par);
            load_stage(pf, pbuf);
            cp_async_mbar_arrive(full_mb(pbuf));
        }
    }

    // ---- epilogue: direct fp32 stores (per-warp output, no CTA sync) ----
    const int mwbase = mtile * TILE_M + warp_m * 64;
    const int nwbase = ntile * TILE_N + warp_n * 32;
    const int qrow = lane >> 2;          // 0..7
    const int qcol = (lane & 3) * 2;     // 0,2,4,6
    #pragma unroll
    for (int mt = 0; mt < 4; ++mt) {
        #pragma unroll
        for (int nt = 0; nt < 4; ++nt) {
            const int m0 = mwbase + mt * 16 + qrow;
            const int n0 = nwbase + nt * 8 + qcol;
            float2 v0 = make_float2(c[mt][nt][0], c[mt][nt][1]);
            float2 v1 = make_float2(c[mt][nt][2], c[mt][nt][3]);
            *reinterpret_cast<float2*>(out + (size_t)m0 * N_FEAT + n0) = v0;
            *reinterpret_cast<float2*>(out + (size_t)(m0 + 8) * N_FEAT + n0) = v1;
        }
    }
}

// ============================ launch =======================================
extern "C" void kernel_launch(void* const* d_in, const int* in_sizes, int n_in,
                              void* d_out, int out_size) {
    const float* x       = (const float*)d_in[0];
    const int*   wpacked = (const int*)d_in[1];
    const float* wparams = (const float*)d_in[2];
    float* out = (float*)d_out;

    cudaFuncSetAttribute(gemm_f16_kernel, cudaFuncAttributeMaxDynamicSharedMemorySize,
                         SMEM_BYTES);

    const int n4  = (M_ROWS * K_FEAT) / 4;         // 8,388,608 float4s
    const int npk = (N_FEAT * K_FEAT) / 2;         // 8,388,608 packed int32s
    prologue_kernel<<<4096, 256>>>(reinterpret_cast<const float4*>(x), n4,
                                   wpacked, wparams, npk);

    dim3 grid(N_FEAT / TILE_N, M_ROWS / TILE_M);   // (16, 64)
    gemm_f16_kernel<<<grid, 512, SMEM_BYTES>>>(out);
}